// round 14
// baseline (speedup 1.0000x reference)
#include <cuda_runtime.h>
#include <cstdint>

#define BB 32
#define SS 128
#define EE 512
#define FF 2048

// scratch: h = x@W1 + b1  [s][b][f]   (33.5 MB)
__device__ __align__(16) float g_h[(size_t)SS * BB * FF];
// scratch: partial y per K-eighth  [kh][b][s][e]  (8 x 8.4 MB)
__device__ __align__(16) float g_yp[8][(size_t)BB * SS * EE];

#define ASTR 36
#define ABYTES (32 * ASTR * 4)                 // 4608

__device__ __forceinline__ uint32_t smem_u32(const void* p) {
    uint32_t a;
    asm("{ .reg .u64 t; cvta.to.shared.u64 t, %1; cvt.u32.u64 %0, t; }" : "=r"(a) : "l"(p));
    return a;
}
__device__ __forceinline__ void cp16(uint32_t saddr, const float* g) {
    asm volatile("cp.async.cg.shared.global [%0], [%1], 16;" :: "r"(saddr), "l"(g) : "memory");
}
__device__ __forceinline__ void cp_commit() { asm volatile("cp.async.commit_group;" ::: "memory"); }
template<int N> __device__ __forceinline__ void cp_wait() {
    asm volatile("cp.async.wait_group %0;" :: "n"(N) : "memory");
}
__device__ __forceinline__ uint32_t f2tf(float f) {
    uint32_t r; asm("cvt.rna.tf32.f32 %0, %1;" : "=r"(r) : "f"(f)); return r;
}
// D(16x8) += A(16x8,row) * B(8x8,col), tf32 inputs, f32 accum
__device__ __forceinline__ void mma8(float* c, const uint32_t* a, const uint32_t* b) {
    asm volatile("mma.sync.aligned.m16n8k8.row.col.f32.tf32.tf32.f32 "
        "{%0,%1,%2,%3}, {%4,%5,%6,%7}, {%8,%9}, {%0,%1,%2,%3};"
        : "+f"(c[0]), "+f"(c[1]), "+f"(c[2]), "+f"(c[3])
        : "r"(a[0]), "r"(a[1]), "r"(a[2]), "r"(a[3]), "r"(b[0]), "r"(b[1]));
}

// ---------------------------------------------------------------------------
// R9 inner pipeline (2-stage, 2 syncs/chunk), re-tiled:
//  G2=false: grid (16,128): s=by, ft=bx*128  (N=128, K=512, 2048 tiles)
//            h[s][b][ft:+128] = x[b][s][:] @ W1[s][:, ft:] + b1
//  G2=true : grid (16,128): s=by, eh=bx>>3, kh=bx&7 (N=256, K=256, 2048 tiles)
//            yp[kh][b][s][eh*256:+256] = h[s][b][kh*256:+256] @ W2[s][kslice, ehalf]
// 256 threads = 8 warps. C tile M=32 x N=NTILE. 2 CTAs/SM.
// ---------------------------------------------------------------------------
template<bool G2>
__global__ __launch_bounds__(256, 2) void ffn_kernel(
    const float* __restrict__ x, const float* __restrict__ W,
    const float* __restrict__ bias)
{
    constexpr int NCH   = G2 ? 8 : 16;          // K chunks of 32 per tile
    constexpr int NC    = G2 ? EE : FF;         // W row width
    constexpr int NTILE = G2 ? 256 : 128;
    constexpr int CPW   = NTILE / 8;            // cols per warp
    constexpr int NT    = CPW / 8;              // n-tiles per warp
    constexpr int BSTRc = G2 ? 264 : 136;
    constexpr int BBYTESc = 32 * BSTRc * 4;
    constexpr int BIT   = G2 ? 8 : 4;           // fillB iterations
    constexpr int NSU   = G2 ? 64 : 32;         // 16B units per B row

    extern __shared__ __align__(16) char dyn[];
    float* Apt[2] = { (float*)dyn, (float*)(dyn + ABYTES) };
    float* Bpt[2] = { (float*)(dyn + 2 * ABYTES), (float*)(dyn + 2 * ABYTES + BBYTESc) };
    const uint32_t aAddr[2] = { smem_u32(Apt[0]), smem_u32(Apt[1]) };
    const uint32_t bAddr[2] = { smem_u32(Bpt[0]), smem_u32(Bpt[1]) };

    const int tid = threadIdx.x;
    const int w   = tid >> 5;
    const int l   = tid & 31;
    const int r   = l >> 2;       // groupID
    const int cl  = l & 3;        // threadID-in-group
    const int s   = (int)blockIdx.y;
    const int bx  = (int)blockIdx.x;
    const int ft   = G2 ? (bx >> 3) * 256 : bx * 128;
    const int koff = G2 ? (bx & 7) * 256 : 0;

    auto fillA = [&](int st, int kc) {
        int row = tid >> 3, seg = tid & 7;
        const float* g = G2 ? (g_h + ((size_t)s * BB + row) * FF + koff + kc + seg * 4)
                            : (x   + ((size_t)row * SS + s) * EE + kc + seg * 4);
        cp16(aAddr[st] + row * (ASTR * 4) + seg * 16, g);
    };
    auto fillB = [&](int st, int kc) {
        const float* wb = W + ((size_t)s * (G2 ? FF : EE) + koff + kc) * NC + ft;
        #pragma unroll
        for (int it = 0; it < BIT; it++) {
            int idx = it * 256 + tid;
            int kr = idx / NSU, ns = idx % NSU;
            cp16(bAddr[st] + kr * (BSTRc * 4) + ns * 16, wb + (size_t)kr * NC + ns * 4);
        }
    };

    float acc[2][NT][4] = {};    // [mTile][nTile][reg]

    fillA(0, 0); fillB(0, 0); cp_commit();

    for (int c = 0; c < NCH; c++) {
        const int cur = c & 1;
        if (c + 1 < NCH) {
            fillA(1 - cur, (c + 1) * 32);
            fillB(1 - cur, (c + 1) * 32);
            cp_commit();
            cp_wait<1>();
        } else {
            cp_wait<0>();
        }
        __syncthreads();

        // A fragments (converted once, reused by all n-tiles)
        const float* Ac = Apt[cur];
        uint32_t afr[2][4][4];
        #pragma unroll
        for (int mt = 0; mt < 2; mt++)
            #pragma unroll
            for (int ks = 0; ks < 4; ks++) {
                int rb = mt * 16 + r, kb = ks * 8 + cl;
                afr[mt][ks][0] = f2tf(Ac[rb * ASTR + kb]);
                afr[mt][ks][1] = f2tf(Ac[(rb + 8) * ASTR + kb]);
                afr[mt][ks][2] = f2tf(Ac[rb * ASTR + kb + 4]);
                afr[mt][ks][3] = f2tf(Ac[(rb + 8) * ASTR + kb + 4]);
            }

        const float* Bc = Bpt[cur];
        const int nb = w * CPW + r;
        #pragma unroll
        for (int nt = 0; nt < NT; nt++) {
            #pragma unroll
            for (int ks = 0; ks < 4; ks++) {
                // raw fp32 bits: HMMA.TF32 truncates the mantissa in HW
                uint32_t bfr[2];
                bfr[0] = __float_as_uint(Bc[(ks * 8 + cl) * BSTRc + nb + nt * 8]);
                bfr[1] = __float_as_uint(Bc[(ks * 8 + 4 + cl) * BSTRc + nb + nt * 8]);
                mma8(acc[0][nt], afr[0][ks], bfr);
                mma8(acc[1][nt], afr[1][ks], bfr);
            }
        }
        __syncthreads();
    }

    if (!G2) {
        // h = C + b1
        const float* bp = bias + (size_t)s * NC + ft;
        #pragma unroll
        for (int mt = 0; mt < 2; mt++)
            #pragma unroll
            for (int nt = 0; nt < NT; nt++) {
                int n0 = w * CPW + nt * 8 + 2 * cl;
                int m0 = mt * 16 + r;
                float b0 = bp[n0], b1v = bp[n0 + 1];
                float2 v0 = make_float2(acc[mt][nt][0] + b0, acc[mt][nt][1] + b1v);
                float2 v1 = make_float2(acc[mt][nt][2] + b0, acc[mt][nt][3] + b1v);
                *reinterpret_cast<float2*>(&g_h[((size_t)s * BB + m0) * FF + ft + n0]) = v0;
                *reinterpret_cast<float2*>(&g_h[((size_t)s * BB + m0 + 8) * FF + ft + n0]) = v1;
            }
    } else {
        // raw partial y (bias/residual deferred to LN kernel)
        float* yp = g_yp[bx & 7];
        #pragma unroll
        for (int mt = 0; mt < 2; mt++)
            #pragma unroll
            for (int nt = 0; nt < NT; nt++) {
                int n0 = w * CPW + nt * 8 + 2 * cl;
                int m0 = mt * 16 + r;
                *reinterpret_cast<float2*>(&yp[((size_t)m0 * SS + s) * EE + ft + n0])
                    = make_float2(acc[mt][nt][0], acc[mt][nt][1]);
                *reinterpret_cast<float2*>(&yp[((size_t)(m0 + 8) * SS + s) * EE + ft + n0])
                    = make_float2(acc[mt][nt][2], acc[mt][nt][3]);
            }
    }
}

// ---------------------------------------------------------------------------
// LN finalize: y = sum_kh yp[kh] + b2 + x;  out = (y-mu)*rsqrt(var+eps)*g + b
// grid 128 (one CTA per s), 256 threads, y staged in 64KB smem.
// ---------------------------------------------------------------------------
__global__ __launch_bounds__(256) void ln_kernel(
    const float* __restrict__ x, const float* __restrict__ b2,
    const float* __restrict__ gamma, const float* __restrict__ beta,
    float* __restrict__ out)
{
    extern __shared__ __align__(16) float ys[];   // [32][512]
    const int s   = blockIdx.x;
    const int tid = threadIdx.x;
    const int w   = tid >> 5;
    const int l   = tid & 31;

    #pragma unroll
    for (int j = 0; j < 4; j++) {
        int b = w * 4 + j;
        const size_t off = ((size_t)b * SS + s) * EE;
        const float4* xp = reinterpret_cast<const float4*>(x + off);
        const float4* bp = reinterpret_cast<const float4*>(b2 + (size_t)s * EE);
        float4* yr = reinterpret_cast<float4*>(ys + b * EE);
        float sum = 0.f, sq = 0.f;
        #pragma unroll
        for (int i = 0; i < 4; i++) {
            int idx = l + i * 32;
            float4 xv = xp[idx], bb = bp[idx];
            float4 y;
            y.x = bb.x + xv.x; y.y = bb.y + xv.y;
            y.z = bb.z + xv.z; y.w = bb.w + xv.w;
            #pragma unroll
            for (int kh = 0; kh < 8; kh++) {
                float4 p = reinterpret_cast<const float4*>(g_yp[kh] + off)[idx];
                y.x += p.x; y.y += p.y; y.z += p.z; y.w += p.w;
            }
            yr[idx] = y;
            sum += y.x + y.y + y.z + y.w;
            sq  += y.x * y.x + y.y * y.y + y.z * y.z + y.w * y.w;
        }
        #pragma unroll
        for (int o = 16; o > 0; o >>= 1) {
            sum += __shfl_xor_sync(0xffffffffu, sum, o);
            sq  += __shfl_xor_sync(0xffffffffu, sq,  o);
        }
        float mu = sum * (1.f / EE);
        float rs = rsqrtf(sq * (1.f / EE) - mu * mu + 1e-5f);
        float4* op = reinterpret_cast<float4*>(out + off);
        const float4* gp = reinterpret_cast<const float4*>(gamma);
        const float4* ep = reinterpret_cast<const float4*>(beta);
        #pragma unroll
        for (int i = 0; i < 4; i++) {
            int idx = l + i * 32;
            float4 y = yr[idx], g4 = gp[idx], e4 = ep[idx];
            float4 v;
            v.x = (y.x - mu) * rs * g4.x + e4.x;
            v.y = (y.y - mu) * rs * g4.y + e4.y;
            v.z = (y.z - mu) * rs * g4.z + e4.z;
            v.w = (y.w - mu) * rs * g4.w + e4.w;
            op[idx] = v;
        }
    }
}

extern "C" void kernel_launch(void* const* d_in, const int* in_sizes, int n_in,
                              void* d_out, int out_size) {
    const float* x     = (const float*)d_in[0];
    const float* W1    = (const float*)d_in[1];
    const float* b1    = (const float*)d_in[2];
    const float* W2    = (const float*)d_in[3];
    const float* b2    = (const float*)d_in[4];
    const float* gamma = (const float*)d_in[5];
    const float* beta  = (const float*)d_in[6];
    float* out = (float*)d_out;

    const int dyn1 = 2 * (ABYTES + 32 * 136 * 4);   // 44032
    const int dyn2 = 2 * (ABYTES + 32 * 264 * 4);   // 76800

    cudaFuncSetAttribute(ffn_kernel<false>,
                         cudaFuncAttributeMaxDynamicSharedMemorySize, dyn1);
    cudaFuncSetAttribute(ffn_kernel<true>,
                         cudaFuncAttributeMaxDynamicSharedMemorySize, dyn2);
    cudaFuncSetAttribute(ln_kernel,
                         cudaFuncAttributeMaxDynamicSharedMemorySize, BB * EE * 4);

    ffn_kernel<false><<<dim3(16, SS), 256, dyn1>>>(x, W1, b1);
    ffn_kernel<true ><<<dim3(16, SS), 256, dyn2>>>(x, W2, nullptr);
    ln_kernel<<<SS, 256, BB * EE * 4>>>(x, b2, gamma, beta, out);
}